// round 8
// baseline (speedup 1.0000x reference)
#include <cuda_runtime.h>
#include <cstdint>

#define DIM 128
#define NPAD 50048
#define NREL 9

__device__ float g_hr[(size_t)8 * NPAD * DIM];
// W preconverted to tf32, fragment-major: [rel][ks(16)][nt(16)][lane(32)] float2
__device__ float g_wtf[(size_t)NREL * 16 * 16 * 32 * 2];

#define NTHREADS 256
#define ROWS 64            // CTA node rows
#define XBLK 132           // floats per (mt,ks) fragment block (128 + 4 pad)
#define XS_FLOATS (4 * 16 * XBLK)             // 8448  (33.8 KB)
#define WB_FLOATS (16 * 16 * 32 * 2)          // 16384 (64 KB)
#define SMEM_BYTES ((XS_FLOATS + WB_FLOATS) * 4)   // 99328 -> 2 CTAs/SM

__device__ __forceinline__ uint32_t f2tf32(float f) {
    uint32_t o;
    asm("cvt.rna.tf32.f32 %0, %1;" : "=r"(o) : "f"(f));
    return o;
}

#define MMA_TF32(d, a, b0, b1)                                                  \
    asm volatile("mma.sync.aligned.m16n8k8.row.col.f32.tf32.tf32.f32 "          \
                 "{%0,%1,%2,%3}, {%4,%5,%6,%7}, {%8,%9}, {%0,%1,%2,%3};"        \
                 : "+f"((d)[0]), "+f"((d)[1]), "+f"((d)[2]), "+f"((d)[3])       \
                 : "r"((a)[0]), "r"((a)[1]), "r"((a)[2]), "r"((a)[3]),          \
                   "r"(b0), "r"(b1))

__device__ __forceinline__ void cp16(float* s, const float* g) {
    uint32_t sa = (uint32_t)__cvta_generic_to_shared(s);
    asm volatile("cp.async.cg.shared.global [%0], [%1], 16;" :: "r"(sa), "l"(g));
}

__device__ __forceinline__ void issue_w(float* buf, const float* src, int tid) {
#pragma unroll
    for (int i = tid; i < WB_FLOATS / 4; i += NTHREADS)
        cp16(buf + i * 4, src + i * 4);
    asm volatile("cp.async.commit_group;" ::: "memory");
}

// ---------------------------------------------------------------------------
// Prologue: convert 9 W matrices to tf32, fragment-major.
// ---------------------------------------------------------------------------
__global__ void conv_w(const float* __restrict__ w, const float* __restrict__ sw) {
    int idx = blockIdx.x * 256 + threadIdx.x;
    if (idx >= NREL * 16 * 16 * 32) return;
    int lane = idx & 31;
    int nt = (idx >> 5) & 15;
    int ks = (idx >> 9) & 15;
    int rel = idx >> 13;
    const float* W = (rel < 8) ? (w + (size_t)rel * DIM * DIM) : sw;
    int k = ks * 8 + (lane & 3);
    int n = nt * 8 + (lane >> 2);
    float2 o;
    o.x = __uint_as_float(f2tf32(W[(size_t)k * DIM + n]));
    o.y = __uint_as_float(f2tf32(W[(size_t)(k + 4) * DIM + n]));
    ((float2*)g_wtf)[idx] = o;
}

// ---------------------------------------------------------------------------
// GEMM: CTA = 64 node rows x 128 cols x 9 relations; 256 thr = 8 warps
// (4 m-blocks x 2 n-halves), warp tile 16x64. 2 CTAs/SM.
// W: single 64KB smem buffer, prefetched for rel+1 during epilogue of rel.
// ---------------------------------------------------------------------------
__global__ void __launch_bounds__(NTHREADS, 2)
rgcn_gemm_mma(const float* __restrict__ x,
              const float* __restrict__ bias,
              float* __restrict__ out,
              int n_nodes) {
    extern __shared__ float smem[];
    float* Xs = smem;                    // fragment-major X (4 m-blocks)
    float* Ws = smem + XS_FLOATS;        // single W buffer

    const int tid = threadIdx.x;
    const int wid = tid >> 5, lane = tid & 31;
    const int row0 = blockIdx.x * ROWS;
    const int wmt = wid & 3;             // m-block 0..3
    const int wnt = (wid >> 2) * 8;      // n-subtile base: 0 or 8

    issue_w(Ws, g_wtf, tid);

    // ---- X tile fill: fragment-major, tf32-converted once ----
#pragma unroll
    for (int i = tid; i < ROWS * 32; i += NTHREADS) {
        int r = i >> 5, c4 = i & 31;
        int node = row0 + r;
        float4 v = (node < n_nodes) ? *(const float4*)(x + (size_t)node * DIM + c4 * 4)
                                    : make_float4(0.f, 0.f, 0.f, 0.f);
        int mt = r >> 4, ks = c4 >> 1;
        int reg = (((r & 15) >= 8) ? 1 : 0) + (c4 & 1) * 2;
        float* base = Xs + (mt * 16 + ks) * XBLK + (r & 7) * 16 + reg;
        base[0]  = __uint_as_float(f2tf32(v.x));
        base[4]  = __uint_as_float(f2tf32(v.y));
        base[8]  = __uint_as_float(f2tf32(v.z));
        base[12] = __uint_as_float(f2tf32(v.w));
    }

    const int lr = lane >> 2;
    const int lc = (lane & 3) * 2;

    for (int rel = 0; rel < NREL; ++rel) {
        asm volatile("cp.async.wait_group 0;" ::: "memory");
        __syncthreads();                 // W[rel] visible; Xs ready (rel==0)

        float c[8][4];
#pragma unroll
        for (int i = 0; i < 8; i++)
#pragma unroll
            for (int j = 0; j < 4; j++) c[i][j] = 0.0f;

        uint32_t Af[2][4], Bf[2][8][2];
        *(float4*)Af[0] = *(const float4*)(Xs + (wmt * 16 + 0) * XBLK + lane * 4);
#pragma unroll
        for (int nt = 0; nt < 8; nt++)
            *(float2*)Bf[0][nt] = *(const float2*)(Ws + ((wnt + nt) * 32 + lane) * 2);

#pragma unroll
        for (int ks = 0; ks < 16; ks++) {
            const int cur = ks & 1, nxt = cur ^ 1;
            if (ks < 15) {
                *(float4*)Af[nxt] =
                    *(const float4*)(Xs + (wmt * 16 + ks + 1) * XBLK + lane * 4);
#pragma unroll
                for (int nt = 0; nt < 8; nt++)
                    *(float2*)Bf[nxt][nt] =
                        *(const float2*)(Ws + (((ks + 1) * 16 + wnt + nt) * 32 + lane) * 2);
            }
#pragma unroll
            for (int nt = 0; nt < 8; nt++)
                MMA_TF32(c[nt], Af[cur], Bf[cur][nt][0], Bf[cur][nt][1]);
        }

        __syncthreads();                 // all warps done reading Ws
        if (rel + 1 < NREL)
            issue_w(Ws, g_wtf + (size_t)(rel + 1) * WB_FLOATS, tid);

        // ---- epilogue (overlaps the W prefetch) ----
        if (rel < 8) {
            float* base = g_hr + ((size_t)rel * NPAD + row0) * DIM;
#pragma unroll
            for (int nt = 0; nt < 8; nt++) {
                int r = wmt * 16 + lr;
                int cc = (wnt + nt) * 8 + lc;
                *(float2*)(base + (size_t)r * DIM + cc)       = make_float2(c[nt][0], c[nt][1]);
                *(float2*)(base + (size_t)(r + 8) * DIM + cc) = make_float2(c[nt][2], c[nt][3]);
            }
        } else {
#pragma unroll
            for (int nt = 0; nt < 8; nt++) {
                int r = wmt * 16 + lr;
                int cc = (wnt + nt) * 8 + lc;
                float b0 = bias[cc], b1 = bias[cc + 1];
                int g0 = row0 + r, g1 = row0 + r + 8;
                if (g0 < n_nodes)
                    *(float2*)(out + (size_t)g0 * DIM + cc) =
                        make_float2(c[nt][0] + b0, c[nt][1] + b1);
                if (g1 < n_nodes)
                    *(float2*)(out + (size_t)g1 * DIM + cc) =
                        make_float2(c[nt][2] + b0, c[nt][3] + b1);
            }
        }
    }
}

// ---------------------------------------------------------------------------
// Scatter: 4 edges/warp (MLP=4), ld.global.cg gather, red.v4 into out[dst].
// ---------------------------------------------------------------------------
__device__ __forceinline__ float4 ldcg4(const float* p) {
    float4 v;
    asm volatile("ld.global.cg.v4.f32 {%0,%1,%2,%3}, [%4];"
                 : "=f"(v.x), "=f"(v.y), "=f"(v.z), "=f"(v.w) : "l"(p));
    return v;
}

__global__ void rgcn_scatter(const int* __restrict__ ei,
                             const int* __restrict__ et,
                             float* __restrict__ out,
                             int n_edges) {
    int gw = (blockIdx.x * blockDim.x + threadIdx.x) >> 5;
    int lane = threadIdx.x & 31;
    int e0 = gw * 4;
    if (e0 >= n_edges) return;

    int s[4], d[4], r[4];
    int cnt = min(4, n_edges - e0);
#pragma unroll
    for (int j = 0; j < 4; j++) {
        int e = e0 + ((j < cnt) ? j : 0);
        s[j] = ei[e]; d[j] = ei[n_edges + e]; r[j] = et[e];
    }
    float4 v[4];
#pragma unroll
    for (int j = 0; j < 4; j++)
        v[j] = ldcg4(g_hr + ((size_t)r[j] * NPAD + (size_t)s[j]) * DIM + lane * 4);
#pragma unroll
    for (int j = 0; j < 4; j++) {
        if (j < cnt) {
            float* q = out + (size_t)d[j] * DIM + lane * 4;
            asm volatile("red.global.add.v4.f32 [%0], {%1, %2, %3, %4};"
                         :: "l"(q), "f"(v[j].x), "f"(v[j].y), "f"(v[j].z), "f"(v[j].w)
                         : "memory");
        }
    }
}

__global__ void rgcn_relu(float* __restrict__ out, int n4) {
    int i = blockIdx.x * blockDim.x + threadIdx.x;
    if (i < n4) {
        float4 v = ((float4*)out)[i];
        v.x = fmaxf(v.x, 0.0f); v.y = fmaxf(v.y, 0.0f);
        v.z = fmaxf(v.z, 0.0f); v.w = fmaxf(v.w, 0.0f);
        ((float4*)out)[i] = v;
    }
}

// ---------------------------------------------------------------------------
extern "C" void kernel_launch(void* const* d_in, const int* in_sizes, int n_in,
                              void* d_out, int out_size) {
    const float* x    = (const float*)d_in[0];
    const float* w    = (const float*)d_in[1];
    const float* sw   = (const float*)d_in[2];
    const float* bias = (const float*)d_in[3];
    const int* ei = (const int*)d_in[4];
    const int* et = (const int*)d_in[5];

    int n_nodes = in_sizes[0] / DIM;
    int n_edges = in_sizes[5];
    float* out = (float*)d_out;

    cudaFuncSetAttribute(rgcn_gemm_mma, cudaFuncAttributeMaxDynamicSharedMemorySize,
                         SMEM_BYTES);

    int cw = (NREL * 16 * 16 * 32 + 255) / 256;
    conv_w<<<cw, 256>>>(w, sw);

    int nb = (n_nodes + ROWS - 1) / ROWS;
    rgcn_gemm_mma<<<nb, NTHREADS, SMEM_BYTES>>>(x, bias, out, n_nodes);

    int n_warps = (n_edges + 3) / 4;
    long long total_threads = (long long)n_warps * 32;
    int blocks = (int)((total_threads + 255) / 256);
    rgcn_scatter<<<blocks, 256>>>(ei, et, out, n_edges);

    int n4 = n_nodes * DIM / 4;
    rgcn_relu<<<(n4 + 255) / 256, 256>>>(out, n4);
}

// round 10
// speedup vs baseline: 1.0547x; 1.0547x over previous
#include <cuda_runtime.h>
#include <cstdint>

#define DIM 128
#define NPAD 50048
#define NREL 9

__device__ float g_hr[(size_t)8 * NPAD * DIM];
// W tf32 fragment-major for direct L2-resident LDG:
// [rel][ks(16)][nh(2)][nt(8)][lane(32)] x float2
__device__ float g_wtf[(size_t)NREL * 16 * 2 * 8 * 32 * 2];

#define NTHREADS 256
#define XBLK 132   // floats per (mt,ks) fragment block (128 + 4 pad)
#define XS_FLOATS (8 * 16 * XBLK)          // 16896 floats = 67.6 KB
#define SMEM_BYTES (XS_FLOATS * 4)

__device__ __forceinline__ uint32_t f2tf32(float f) {
    uint32_t o;
    asm("cvt.rna.tf32.f32 %0, %1;" : "=r"(o) : "f"(f));
    return o;
}

#define MMA_TF32(d, a, b0, b1)                                                  \
    asm volatile("mma.sync.aligned.m16n8k8.row.col.f32.tf32.tf32.f32 "          \
                 "{%0,%1,%2,%3}, {%4,%5,%6,%7}, {%8,%9}, {%0,%1,%2,%3};"        \
                 : "+f"((d)[0]), "+f"((d)[1]), "+f"((d)[2]), "+f"((d)[3])       \
                 : "r"((a)[0]), "r"((a)[1]), "r"((a)[2]), "r"((a)[3]),          \
                   "r"(b0), "r"(b1))

// ---------------------------------------------------------------------------
// Prologue: convert 9 W matrices to tf32, fragment-major (new layout).
// b0 = W[k][n], b1 = W[k+4][n]; k = ks*8+(lane&3), n = (nh*8+nt)*8+(lane>>2).
// ---------------------------------------------------------------------------
__global__ void conv_w(const float* __restrict__ w, const float* __restrict__ sw) {
    int idx = blockIdx.x * 256 + threadIdx.x;
    if (idx >= NREL * 16 * 2 * 8 * 32) return;
    int lane = idx & 31;
    int nt  = (idx >> 5) & 7;
    int nh  = (idx >> 8) & 1;
    int ks  = (idx >> 9) & 15;
    int rel = idx >> 13;
    const float* W = (rel < 8) ? (w + (size_t)rel * DIM * DIM) : sw;
    int k = ks * 8 + (lane & 3);
    int n = (nh * 8 + nt) * 8 + (lane >> 2);
    float2 o;
    o.x = __uint_as_float(f2tf32(W[(size_t)k * DIM + n]));
    o.y = __uint_as_float(f2tf32(W[(size_t)(k + 4) * DIM + n]));
    ((float2*)g_wtf)[idx] = o;
}

// ---------------------------------------------------------------------------
// GEMM: CTA = 128 node rows x 9 relations; 256 thr = 8 warps (4m x 2n),
// warp tile 32x64. X in smem (fragment-major); B streamed from L2 via LDG.
// No smem W staging, single __syncthreads, 2 CTAs/SM.
// ---------------------------------------------------------------------------
__global__ void __launch_bounds__(NTHREADS, 2)
rgcn_gemm_mma(const float* __restrict__ x,
              const float* __restrict__ bias,
              float* __restrict__ out,
              int n_nodes) {
    extern __shared__ float smem[];
    float* Xs = smem;

    const int tid = threadIdx.x;
    const int wid = tid >> 5, lane = tid & 31;
    const int row0 = blockIdx.x * 128;
    const int wmt = (wid & 3) * 2;   // warp's first m-subtile (of 8)
    const int wnh = wid >> 2;        // warp's n-half (0/1)
    const int wnt = wnh * 8;

    // ---- X tile fill: fragment-major, tf32-converted once ----
#pragma unroll
    for (int i = tid; i < 4096; i += NTHREADS) {
        int r = i >> 5, c4 = i & 31;
        int node = row0 + r;
        float4 v = (node < n_nodes) ? *(const float4*)(x + (size_t)node * DIM + c4 * 4)
                                    : make_float4(0.f, 0.f, 0.f, 0.f);
        int mt = r >> 4, ks = c4 >> 1;
        int reg = (((r & 15) >= 8) ? 1 : 0) + (c4 & 1) * 2;
        float* base = Xs + (mt * 16 + ks) * XBLK + (r & 7) * 16 + reg;
        base[0]  = __uint_as_float(f2tf32(v.x));
        base[4]  = __uint_as_float(f2tf32(v.y));
        base[8]  = __uint_as_float(f2tf32(v.z));
        base[12] = __uint_as_float(f2tf32(v.w));
    }
    __syncthreads();

    const int lr = lane >> 2;
    const int lc = (lane & 3) * 2;
    // B fragment stream base for this warp: [rel][ks][wnh][nt][lane]
    const float2* wbase = (const float2*)g_wtf + ((size_t)wnh * 8 * 32) + lane;

    for (int rel = 0; rel < NREL; ++rel) {
        const float2* wrel = wbase + (size_t)rel * (16 * 2 * 8 * 32);

        float c[16][4];
#pragma unroll
        for (int i = 0; i < 16; i++)
#pragma unroll
            for (int j = 0; j < 4; j++) c[i][j] = 0.0f;

        uint32_t Af[2][2][4], Bf[2][8][2];
        // prime ks=0
#pragma unroll
        for (int mt = 0; mt < 2; mt++)
            *(float4*)Af[0][mt] = *(const float4*)(Xs + ((wmt + mt) * 16 + 0) * XBLK + lane * 4);
#pragma unroll
        for (int nt = 0; nt < 8; nt++)
            *(float2*)Bf[0][nt] = wrel[nt * 32];

#pragma unroll
        for (int ks = 0; ks < 16; ks++) {
            const int cur = ks & 1, nxt = cur ^ 1;
            if (ks < 15) {
#pragma unroll
                for (int mt = 0; mt < 2; mt++)
                    *(float4*)Af[nxt][mt] =
                        *(const float4*)(Xs + ((wmt + mt) * 16 + ks + 1) * XBLK + lane * 4);
                const float2* wks = wrel + (size_t)(ks + 1) * (2 * 8 * 32);
#pragma unroll
                for (int nt = 0; nt < 8; nt++)
                    *(float2*)Bf[nxt][nt] = wks[nt * 32];
            }
#pragma unroll
            for (int nt = 0; nt < 8; nt++) {
                MMA_TF32(c[nt],     Af[cur][0], Bf[cur][nt][0], Bf[cur][nt][1]);
                MMA_TF32(c[8 + nt], Af[cur][1], Bf[cur][nt][0], Bf[cur][nt][1]);
            }
        }

        // ---- epilogue ----
        if (rel < 8) {
            float* base = g_hr + ((size_t)rel * NPAD + row0) * DIM;
#pragma unroll
            for (int mt = 0; mt < 2; mt++)
#pragma unroll
                for (int nt = 0; nt < 8; nt++) {
                    int r = (wmt + mt) * 16 + lr;
                    int cc = (wnt + nt) * 8 + lc;
                    *(float2*)(base + (size_t)r * DIM + cc) =
                        make_float2(c[mt * 8 + nt][0], c[mt * 8 + nt][1]);
                    *(float2*)(base + (size_t)(r + 8) * DIM + cc) =
                        make_float2(c[mt * 8 + nt][2], c[mt * 8 + nt][3]);
                }
        } else {
#pragma unroll
            for (int mt = 0; mt < 2; mt++)
#pragma unroll
                for (int nt = 0; nt < 8; nt++) {
                    int r = (wmt + mt) * 16 + lr;
                    int cc = (wnt + nt) * 8 + lc;
                    float b0 = bias[cc], b1 = bias[cc + 1];
                    int g0 = row0 + r, g1 = row0 + r + 8;
                    if (g0 < n_nodes)
                        *(float2*)(out + (size_t)g0 * DIM + cc) =
                            make_float2(c[mt * 8 + nt][0] + b0, c[mt * 8 + nt][1] + b1);
                    if (g1 < n_nodes)
                        *(float2*)(out + (size_t)g1 * DIM + cc) =
                            make_float2(c[mt * 8 + nt][2] + b0, c[mt * 8 + nt][3] + b1);
                }
        }
    }
}

// ---------------------------------------------------------------------------
// Scatter: 4 edges/warp (MLP=4), ld.global.cg gather, red.v4 into out[dst].
// ---------------------------------------------------------------------------
__device__ __forceinline__ float4 ldcg4(const float* p) {
    float4 v;
    asm volatile("ld.global.cg.v4.f32 {%0,%1,%2,%3}, [%4];"
                 : "=f"(v.x), "=f"(v.y), "=f"(v.z), "=f"(v.w) : "l"(p));
    return v;
}

__global__ void rgcn_scatter(const int* __restrict__ ei,
                             const int* __restrict__ et,
                             float* __restrict__ out,
                             int n_edges) {
    int gw = (blockIdx.x * blockDim.x + threadIdx.x) >> 5;
    int lane = threadIdx.x & 31;
    int e0 = gw * 4;
    if (e0 >= n_edges) return;

    int s[4], d[4], r[4];
    int cnt = min(4, n_edges - e0);
#pragma unroll
    for (int j = 0; j < 4; j++) {
        int e = e0 + ((j < cnt) ? j : 0);
        s[j] = ei[e]; d[j] = ei[n_edges + e]; r[j] = et[e];
    }
    float4 v[4];
#pragma unroll
    for (int j = 0; j < 4; j++)
        v[j] = ldcg4(g_hr + ((size_t)r[j] * NPAD + (size_t)s[j]) * DIM + lane * 4);
#pragma unroll
    for (int j = 0; j < 4; j++) {
        if (j < cnt) {
            float* q = out + (size_t)d[j] * DIM + lane * 4;
            asm volatile("red.global.add.v4.f32 [%0], {%1, %2, %3, %4};"
                         :: "l"(q), "f"(v[j].x), "f"(v[j].y), "f"(v[j].z), "f"(v[j].w)
                         : "memory");
        }
    }
}

__global__ void rgcn_relu(float* __restrict__ out, int n4) {
    int i = blockIdx.x * blockDim.x + threadIdx.x;
    if (i < n4) {
        float4 v = ((float4*)out)[i];
        v.x = fmaxf(v.x, 0.0f); v.y = fmaxf(v.y, 0.0f);
        v.z = fmaxf(v.z, 0.0f); v.w = fmaxf(v.w, 0.0f);
        ((float4*)out)[i] = v;
    }
}

// ---------------------------------------------------------------------------
extern "C" void kernel_launch(void* const* d_in, const int* in_sizes, int n_in,
                              void* d_out, int out_size) {
    const float* x    = (const float*)d_in[0];
    const float* w    = (const float*)d_in[1];
    const float* sw   = (const float*)d_in[2];
    const float* bias = (const float*)d_in[3];
    const int* ei = (const int*)d_in[4];
    const int* et = (const int*)d_in[5];

    int n_nodes = in_sizes[0] / DIM;
    int n_edges = in_sizes[5];
    float* out = (float*)d_out;

    cudaFuncSetAttribute(rgcn_gemm_mma, cudaFuncAttributeMaxDynamicSharedMemorySize,
                         SMEM_BYTES);

    int cw = (NREL * 16 * 2 * 8 * 32 + 255) / 256;
    conv_w<<<cw, 256>>>(w, sw);

    int nb = (n_nodes + 127) / 128;
    rgcn_gemm_mma<<<nb, NTHREADS, SMEM_BYTES>>>(x, bias, out, n_nodes);

    int n_warps = (n_edges + 3) / 4;
    long long total_threads = (long long)n_warps * 32;
    int blocks = (int)((total_threads + 255) / 256);
    rgcn_scatter<<<blocks, 256>>>(ei, et, out, n_edges);

    int n4 = n_nodes * DIM / 4;
    rgcn_relu<<<(n4 + 255) / 256, 256>>>(out, n4);
}

// round 11
// speedup vs baseline: 1.1593x; 1.0992x over previous
#include <cuda_runtime.h>
#include <cuda_fp16.h>
#include <cstdint>

#define DIM 128
#define NPAD 50048
#define NREL 9

// hr messages stored in fp16: 8 * 50048 * 128 * 2B = 102.5 MB
__device__ __half g_hr_h[(size_t)8 * NPAD * DIM];
// W preconverted to tf32, fragment-major: [rel][ks(16)][nt(16)][lane(32)] float2
__device__ float g_wtf[(size_t)NREL * 16 * 16 * 32 * 2];

#define NTHREADS 256
#define XBLK 132   // floats per (mt,ks) fragment block (128 + 4 pad)
#define XS_FLOATS (8 * 16 * XBLK)             // 16896
#define WB_FLOATS (16 * 16 * 32 * 2)          // 16384
#define SMEM_BYTES ((XS_FLOATS + 2 * WB_FLOATS) * 4)   // 198656

__device__ __forceinline__ uint32_t f2tf32(float f) {
    uint32_t o;
    asm("cvt.rna.tf32.f32 %0, %1;" : "=r"(o) : "f"(f));
    return o;
}

#define MMA_TF32(d, a, b0, b1)                                                  \
    asm volatile("mma.sync.aligned.m16n8k8.row.col.f32.tf32.tf32.f32 "          \
                 "{%0,%1,%2,%3}, {%4,%5,%6,%7}, {%8,%9}, {%0,%1,%2,%3};"        \
                 : "+f"((d)[0]), "+f"((d)[1]), "+f"((d)[2]), "+f"((d)[3])       \
                 : "r"((a)[0]), "r"((a)[1]), "r"((a)[2]), "r"((a)[3]),          \
                   "r"(b0), "r"(b1))

__device__ __forceinline__ void cp16(float* s, const float* g) {
    uint32_t sa = (uint32_t)__cvta_generic_to_shared(s);
    asm volatile("cp.async.cg.shared.global [%0], [%1], 16;" :: "r"(sa), "l"(g));
}

__device__ __forceinline__ void issue_w(float* buf, const float* src, int tid) {
#pragma unroll
    for (int i = tid; i < WB_FLOATS / 4; i += NTHREADS)
        cp16(buf + i * 4, src + i * 4);
    asm volatile("cp.async.commit_group;" ::: "memory");
}

// ---------------------------------------------------------------------------
// Prologue: convert 9 W matrices to tf32, fragment-major.
// ---------------------------------------------------------------------------
__global__ void conv_w(const float* __restrict__ w, const float* __restrict__ sw) {
    int idx = blockIdx.x * 256 + threadIdx.x;
    if (idx >= NREL * 16 * 16 * 32) return;
    int lane = idx & 31;
    int nt = (idx >> 5) & 15;
    int ks = (idx >> 9) & 15;
    int rel = idx >> 13;
    const float* W = (rel < 8) ? (w + (size_t)rel * DIM * DIM) : sw;
    int k = ks * 8 + (lane & 3);
    int n = nt * 8 + (lane >> 2);
    float2 o;
    o.x = __uint_as_float(f2tf32(W[(size_t)k * DIM + n]));
    o.y = __uint_as_float(f2tf32(W[(size_t)(k + 4) * DIM + n]));
    ((float2*)g_wtf)[idx] = o;
}

// ---------------------------------------------------------------------------
// GEMM (R7 geometry): CTA = 128 rows x 9 relations; 256 thr, warp tile 32x64.
// Fragment-major smem for X and W; W double-buffered via cp.async.
// rel 0..7 -> g_hr_h (fp16); rel 8 -> out = X@selfW + bias (fp32).
// ---------------------------------------------------------------------------
__global__ void __launch_bounds__(NTHREADS, 1)
rgcn_gemm_mma(const float* __restrict__ x,
              const float* __restrict__ bias,
              float* __restrict__ out,
              int n_nodes) {
    extern __shared__ float smem[];
    float* Xs  = smem;
    float* Ws0 = smem + XS_FLOATS;
    float* Ws1 = Ws0 + WB_FLOATS;

    const int tid = threadIdx.x;
    const int wid = tid >> 5, lane = tid & 31;
    const int row0 = blockIdx.x * 128;
    const int wmt = (wid & 3) * 2;   // warp's first m-subtile (of 8)
    const int wnt = (wid >> 2) * 8;  // warp's first n-subtile (of 16)

    issue_w(Ws0, g_wtf, tid);
    issue_w(Ws1, g_wtf + WB_FLOATS, tid);

    // ---- X tile fill: fragment-major, tf32-converted once ----
#pragma unroll
    for (int i = tid; i < 4096; i += NTHREADS) {
        int r = i >> 5, c4 = i & 31;
        int node = row0 + r;
        float4 v = (node < n_nodes) ? *(const float4*)(x + (size_t)node * DIM + c4 * 4)
                                    : make_float4(0.f, 0.f, 0.f, 0.f);
        int mt = r >> 4, ks = c4 >> 1;
        int reg = (((r & 15) >= 8) ? 1 : 0) + (c4 & 1) * 2;
        float* base = Xs + (mt * 16 + ks) * XBLK + (r & 7) * 16 + reg;
        base[0]  = __uint_as_float(f2tf32(v.x));
        base[4]  = __uint_as_float(f2tf32(v.y));
        base[8]  = __uint_as_float(f2tf32(v.z));
        base[12] = __uint_as_float(f2tf32(v.w));
    }

    const int lr = lane >> 2;
    const int lc = (lane & 3) * 2;

    for (int rel = 0; rel < NREL; ++rel) {
        if (rel == NREL - 1) asm volatile("cp.async.wait_group 0;" ::: "memory");
        else                 asm volatile("cp.async.wait_group 1;" ::: "memory");
        __syncthreads();

        const float* Wb = (rel & 1) ? Ws1 : Ws0;

        float c[16][4];
#pragma unroll
        for (int i = 0; i < 16; i++)
#pragma unroll
            for (int j = 0; j < 4; j++) c[i][j] = 0.0f;

        uint32_t Af[2][2][4], Bf[2][8][2];
#pragma unroll
        for (int mt = 0; mt < 2; mt++)
            *(float4*)Af[0][mt] = *(const float4*)(Xs + ((wmt + mt) * 16 + 0) * XBLK + lane * 4);
#pragma unroll
        for (int nt = 0; nt < 8; nt++)
            *(float2*)Bf[0][nt] = *(const float2*)(Wb + ((0 * 16 + wnt + nt) * 32 + lane) * 2);

#pragma unroll
        for (int ks = 0; ks < 16; ks++) {
            const int cur = ks & 1, nxt = cur ^ 1;
            if (ks < 15) {
#pragma unroll
                for (int mt = 0; mt < 2; mt++)
                    *(float4*)Af[nxt][mt] =
                        *(const float4*)(Xs + ((wmt + mt) * 16 + ks + 1) * XBLK + lane * 4);
#pragma unroll
                for (int nt = 0; nt < 8; nt++)
                    *(float2*)Bf[nxt][nt] =
                        *(const float2*)(Wb + (((ks + 1) * 16 + wnt + nt) * 32 + lane) * 2);
            }
#pragma unroll
            for (int nt = 0; nt < 8; nt++) {
                MMA_TF32(c[nt],     Af[cur][0], Bf[cur][nt][0], Bf[cur][nt][1]);
                MMA_TF32(c[8 + nt], Af[cur][1], Bf[cur][nt][0], Bf[cur][nt][1]);
            }
        }

        __syncthreads();
        if (rel + 2 < NREL)
            issue_w((float*)Wb, g_wtf + (size_t)(rel + 2) * WB_FLOATS, tid);

        // ---- epilogue ----
        if (rel < 8) {
            __half* base = g_hr_h + ((size_t)rel * NPAD + row0) * DIM;
#pragma unroll
            for (int mt = 0; mt < 2; mt++)
#pragma unroll
                for (int nt = 0; nt < 8; nt++) {
                    int r = (wmt + mt) * 16 + lr;
                    int cc = (wnt + nt) * 8 + lc;
                    *(__half2*)(base + (size_t)r * DIM + cc) =
                        __floats2half2_rn(c[mt * 8 + nt][0], c[mt * 8 + nt][1]);
                    *(__half2*)(base + (size_t)(r + 8) * DIM + cc) =
                        __floats2half2_rn(c[mt * 8 + nt][2], c[mt * 8 + nt][3]);
                }
        } else {
#pragma unroll
            for (int mt = 0; mt < 2; mt++)
#pragma unroll
                for (int nt = 0; nt < 8; nt++) {
                    int r = (wmt + mt) * 16 + lr;
                    int cc = (wnt + nt) * 8 + lc;
                    float b0 = bias[cc], b1 = bias[cc + 1];
                    int g0 = row0 + r, g1 = row0 + r + 8;
                    if (g0 < n_nodes)
                        *(float2*)(out + (size_t)g0 * DIM + cc) =
                            make_float2(c[mt * 8 + nt][0] + b0, c[mt * 8 + nt][1] + b1);
                    if (g1 < n_nodes)
                        *(float2*)(out + (size_t)g1 * DIM + cc) =
                            make_float2(c[mt * 8 + nt][2] + b0, c[mt * 8 + nt][3] + b1);
                }
        }
    }
}

// ---------------------------------------------------------------------------
// Scatter: 4 edges/warp (MLP=4). Gather 256B fp16 per edge (8B/lane via
// ld.global.cg.v2.u32), convert to fp32, red.v4 into out[dst].
// ---------------------------------------------------------------------------
__device__ __forceinline__ uint2 ldcg8(const void* p) {
    uint2 v;
    asm volatile("ld.global.cg.v2.u32 {%0,%1}, [%2];" : "=r"(v.x), "=r"(v.y) : "l"(p));
    return v;
}

__global__ void rgcn_scatter(const int* __restrict__ ei,
                             const int* __restrict__ et,
                             float* __restrict__ out,
                             int n_edges) {
    int gw = (blockIdx.x * blockDim.x + threadIdx.x) >> 5;
    int lane = threadIdx.x & 31;
    int e0 = gw * 4;
    if (e0 >= n_edges) return;

    int s[4], d[4], r[4];
    int cnt = min(4, n_edges - e0);
#pragma unroll
    for (int j = 0; j < 4; j++) {
        int e = e0 + ((j < cnt) ? j : 0);
        s[j] = ei[e]; d[j] = ei[n_edges + e]; r[j] = et[e];
    }
    uint2 raw[4];
#pragma unroll
    for (int j = 0; j < 4; j++)
        raw[j] = ldcg8(g_hr_h + ((size_t)r[j] * NPAD + (size_t)s[j]) * DIM + lane * 4);
#pragma unroll
    for (int j = 0; j < 4; j++) {
        if (j < cnt) {
            __half2 h01 = *(__half2*)&raw[j].x;
            __half2 h23 = *(__half2*)&raw[j].y;
            float2 f01 = __half22float2(h01);
            float2 f23 = __half22float2(h23);
            float* q = out + (size_t)d[j] * DIM + lane * 4;
            asm volatile("red.global.add.v4.f32 [%0], {%1, %2, %3, %4};"
                         :: "l"(q), "f"(f01.x), "f"(f01.y), "f"(f23.x), "f"(f23.y)
                         : "memory");
        }
    }
}

__global__ void rgcn_relu(float* __restrict__ out, int n4) {
    int i = blockIdx.x * blockDim.x + threadIdx.x;
    if (i < n4) {
        float4 v = ((float4*)out)[i];
        v.x = fmaxf(v.x, 0.0f); v.y = fmaxf(v.y, 0.0f);
        v.z = fmaxf(v.z, 0.0f); v.w = fmaxf(v.w, 0.0f);
        ((float4*)out)[i] = v;
    }
}

// ---------------------------------------------------------------------------
extern "C" void kernel_launch(void* const* d_in, const int* in_sizes, int n_in,
                              void* d_out, int out_size) {
    const float* x    = (const float*)d_in[0];
    const float* w    = (const float*)d_in[1];
    const float* sw   = (const float*)d_in[2];
    const float* bias = (const float*)d_in[3];
    const int* ei = (const int*)d_in[4];
    const int* et = (const int*)d_in[5];

    int n_nodes = in_sizes[0] / DIM;
    int n_edges = in_sizes[5];
    float* out = (float*)d_out;

    cudaFuncSetAttribute(rgcn_gemm_mma, cudaFuncAttributeMaxDynamicSharedMemorySize,
                         SMEM_BYTES);

    int cw = (NREL * 16 * 16 * 32 + 255) / 256;
    conv_w<<<cw, 256>>>(w, sw);

    int nb = (n_nodes + 127) / 128;
    rgcn_gemm_mma<<<nb, NTHREADS, SMEM_BYTES>>>(x, bias, out, n_nodes);

    int n_warps = (n_edges + 3) / 4;
    long long total_threads = (long long)n_warps * 32;
    int blocks = (int)((total_threads + 255) / 256);
    rgcn_scatter<<<blocks, 256>>>(ei, et, out, n_edges);

    int n4 = n_nodes * DIM / 4;
    rgcn_relu<<<(n4 + 255) / 256, 256>>>(out, n4);
}

// round 12
// speedup vs baseline: 1.5017x; 1.2954x over previous
#include <cuda_runtime.h>
#include <cuda_fp16.h>
#include <cstdint>

#define DIM 128
#define NPAD 50048
#define NREL 9

// hr messages in fp16: 8 * 50048 * 128 * 2B = 102.5 MB
__device__ __half g_hr_h[(size_t)8 * NPAD * DIM];
// W as fp16 B-fragments: [rel][ks(8)][nt(16)][lane(32)] x uint2 (b0,b1)
__device__ uint2 g_wtf_h[(size_t)NREL * 8 * 16 * 32];

#define NTHREADS 256
#define XBLK 132                       // uint32 per (mt,ks) block (128 + 4 pad)
#define XS_U32 (8 * 8 * XBLK)          // 8448 u32 = 33.8 KB
#define WB_U32 (8 * 16 * 32 * 2)       // 8192 u32 = 32 KB per W buffer
#define SMEM_BYTES ((XS_U32 + 2 * WB_U32) * 4)   // 99328 -> 2 CTAs/SM

#define MMA_F16(d, a, b)                                                        \
    asm volatile("mma.sync.aligned.m16n8k16.row.col.f32.f16.f16.f32 "          \
                 "{%0,%1,%2,%3}, {%4,%5,%6,%7}, {%8,%9}, {%0,%1,%2,%3};"        \
                 : "+f"((d)[0]), "+f"((d)[1]), "+f"((d)[2]), "+f"((d)[3])       \
                 : "r"((a)[0]), "r"((a)[1]), "r"((a)[2]), "r"((a)[3]),          \
                   "r"((b)[0]), "r"((b)[1]))

__device__ __forceinline__ void cp16(void* s, const void* g) {
    uint32_t sa = (uint32_t)__cvta_generic_to_shared(s);
    asm volatile("cp.async.cg.shared.global [%0], [%1], 16;" :: "r"(sa), "l"(g));
}

__device__ __forceinline__ void issue_w(uint32_t* buf, const uint32_t* src, int tid) {
#pragma unroll
    for (int i = tid; i < WB_U32 / 4; i += NTHREADS)
        cp16(buf + i * 4, src + i * 4);
    asm volatile("cp.async.commit_group;" ::: "memory");
}

// ---------------------------------------------------------------------------
// Prologue: W -> fp16 B fragments for m16n8k16.
// b0 = (W[k0][n], W[k0+1][n]), b1 = (W[k0+8][n], W[k0+9][n]);
// k0 = ks*16 + (lane&3)*2, n = nt*8 + (lane>>2).
// ---------------------------------------------------------------------------
__global__ void conv_w(const float* __restrict__ w, const float* __restrict__ sw) {
    int idx = blockIdx.x * 256 + threadIdx.x;
    if (idx >= NREL * 8 * 16 * 32) return;
    int lane = idx & 31;
    int nt  = (idx >> 5) & 15;
    int ks  = (idx >> 9) & 7;
    int rel = idx >> 12;
    const float* W = (rel < 8) ? (w + (size_t)rel * DIM * DIM) : sw;
    int k0 = ks * 16 + (lane & 3) * 2;
    int n  = nt * 8 + (lane >> 2);
    __half2 b0 = __floats2half2_rn(W[(size_t)k0 * DIM + n],       W[(size_t)(k0 + 1) * DIM + n]);
    __half2 b1 = __floats2half2_rn(W[(size_t)(k0 + 8) * DIM + n], W[(size_t)(k0 + 9) * DIM + n]);
    uint2 o;
    o.x = *(uint32_t*)&b0;
    o.y = *(uint32_t*)&b1;
    g_wtf_h[idx] = o;
}

// ---------------------------------------------------------------------------
// GEMM: CTA = 128 rows x 9 relations; 256 thr = 8 warps (4m x 2n),
// warp tile 32x64, fp16 m16n8k16, fp32 accum. 2 CTAs/SM.
// rel 0..7 -> g_hr_h (fp16); rel 8 -> out = X@selfW + bias (fp32).
// ---------------------------------------------------------------------------
__global__ void __launch_bounds__(NTHREADS, 2)
rgcn_gemm_mma(const float* __restrict__ x,
              const float* __restrict__ bias,
              float* __restrict__ out,
              int n_nodes) {
    extern __shared__ uint32_t smem[];
    uint32_t* Xs  = smem;                 // fp16 A fragments, fragment-major
    uint32_t* Ws0 = smem + XS_U32;
    uint32_t* Ws1 = Ws0 + WB_U32;

    const int tid = threadIdx.x;
    const int wid = tid >> 5, lane = tid & 31;
    const int row0 = blockIdx.x * 128;
    const int wmt = (wid & 3) * 2;   // first m-subtile (of 8)
    const int wnt = (wid >> 2) * 8;  // first n-subtile (of 16)

    issue_w(Ws0, (const uint32_t*)g_wtf_h, tid);
    issue_w(Ws1, (const uint32_t*)g_wtf_h + WB_U32, tid);

    // ---- X tile fill: fp16 A fragments (a0..a3 per lane per (mt,ks)) ----
    // a0={r,c0,c0+1} a1={r+8,..} a2={r,c0+8,c0+9} a3={r+8,..}; c0=(lane&3)*2.
#pragma unroll
    for (int i = tid; i < 128 * 32; i += NTHREADS) {
        int r = i >> 5, c4 = i & 31;
        int node = row0 + r;
        float4 v = (node < n_nodes) ? *(const float4*)(x + (size_t)node * DIM + c4 * 4)
                                    : make_float4(0.f, 0.f, 0.f, 0.f);
        __half2 p0 = __floats2half2_rn(v.x, v.y);   // col pair cp = 2*c4
        __half2 p1 = __floats2half2_rn(v.z, v.w);   // col pair cp+1
        int mt = r >> 4, lr = r & 15;
        int ks = c4 >> 2;
        int lcp = (2 * c4) & 7;                     // 0,2,4,6
        int lane0 = (lr & 7) * 4 + (lcp & 3);       // even
        int reg = ((lr >= 8) ? 1 : 0) + ((lcp >= 4) ? 2 : 0);
        uint32_t* base = Xs + (mt * 8 + ks) * XBLK + reg;
        base[lane0 * 4]       = *(uint32_t*)&p0;
        base[(lane0 + 1) * 4] = *(uint32_t*)&p1;
    }

    const int lr = lane >> 2;
    const int lc = (lane & 3) * 2;

    for (int rel = 0; rel < NREL; ++rel) {
        if (rel == NREL - 1) asm volatile("cp.async.wait_group 0;" ::: "memory");
        else                 asm volatile("cp.async.wait_group 1;" ::: "memory");
        __syncthreads();

        const uint32_t* Wb = (rel & 1) ? Ws1 : Ws0;

        float c[16][4];
#pragma unroll
        for (int i = 0; i < 16; i++)
#pragma unroll
            for (int j = 0; j < 4; j++) c[i][j] = 0.0f;

        uint32_t Af[2][2][4];
#pragma unroll
        for (int mt = 0; mt < 2; mt++)
            *(uint4*)Af[0][mt] = *(const uint4*)(Xs + ((wmt + mt) * 8 + 0) * XBLK + lane * 4);

#pragma unroll
        for (int ks = 0; ks < 8; ks++) {
            const int cur = ks & 1, nxt = cur ^ 1;
            uint32_t Bf[8][2];
#pragma unroll
            for (int nt = 0; nt < 8; nt++)
                *(uint2*)Bf[nt] = *(const uint2*)(Wb + ((ks * 16 + wnt + nt) * 32 + lane) * 2);
            if (ks < 7) {
#pragma unroll
                for (int mt = 0; mt < 2; mt++)
                    *(uint4*)Af[nxt][mt] =
                        *(const uint4*)(Xs + ((wmt + mt) * 8 + ks + 1) * XBLK + lane * 4);
            }
#pragma unroll
            for (int nt = 0; nt < 8; nt++) {
                MMA_F16(c[nt],     Af[cur][0], Bf[nt]);
                MMA_F16(c[8 + nt], Af[cur][1], Bf[nt]);
            }
        }

        __syncthreads();
        if (rel + 2 < NREL)
            issue_w((uint32_t*)Wb, (const uint32_t*)g_wtf_h + (size_t)(rel + 2) * WB_U32, tid);

        // ---- epilogue ----
        if (rel < 8) {
            __half* base = g_hr_h + ((size_t)rel * NPAD + row0) * DIM;
#pragma unroll
            for (int mt = 0; mt < 2; mt++)
#pragma unroll
                for (int nt = 0; nt < 8; nt++) {
                    int r = (wmt + mt) * 16 + lr;
                    int cc = (wnt + nt) * 8 + lc;
                    *(__half2*)(base + (size_t)r * DIM + cc) =
                        __floats2half2_rn(c[mt * 8 + nt][0], c[mt * 8 + nt][1]);
                    *(__half2*)(base + (size_t)(r + 8) * DIM + cc) =
                        __floats2half2_rn(c[mt * 8 + nt][2], c[mt * 8 + nt][3]);
                }
        } else {
#pragma unroll
            for (int mt = 0; mt < 2; mt++)
#pragma unroll
                for (int nt = 0; nt < 8; nt++) {
                    int r = (wmt + mt) * 16 + lr;
                    int cc = (wnt + nt) * 8 + lc;
                    float b0 = bias[cc], b1 = bias[cc + 1];
                    int g0 = row0 + r, g1 = row0 + r + 8;
                    if (g0 < n_nodes)
                        *(float2*)(out + (size_t)g0 * DIM + cc) =
                            make_float2(c[mt * 8 + nt][0] + b0, c[mt * 8 + nt][1] + b1);
                    if (g1 < n_nodes)
                        *(float2*)(out + (size_t)g1 * DIM + cc) =
                            make_float2(c[mt * 8 + nt][2] + b0, c[mt * 8 + nt][3] + b1);
                }
        }
    }
}

// ---------------------------------------------------------------------------
// Scatter: 4 edges/warp (MLP=4). Gather 256B fp16 per edge (8B/lane),
// convert to fp32, red.v4 into out[dst].
// ---------------------------------------------------------------------------
__device__ __forceinline__ uint2 ldcg8(const void* p) {
    uint2 v;
    asm volatile("ld.global.cg.v2.u32 {%0,%1}, [%2];" : "=r"(v.x), "=r"(v.y) : "l"(p));
    return v;
}

__global__ void rgcn_scatter(const int* __restrict__ ei,
                             const int* __restrict__ et,
                             float* __restrict__ out,
                             int n_edges) {
    int gw = (blockIdx.x * blockDim.x + threadIdx.x) >> 5;
    int lane = threadIdx.x & 31;
    int e0 = gw * 4;
    if (e0 >= n_edges) return;

    int s[4], d[4], r[4];
    int cnt = min(4, n_edges - e0);
#pragma unroll
    for (int j = 0; j < 4; j++) {
        int e = e0 + ((j < cnt) ? j : 0);
        s[j] = ei[e]; d[j] = ei[n_edges + e]; r[j] = et[e];
    }
    uint2 raw[4];
#pragma unroll
    for (int j = 0; j < 4; j++)
        raw[j] = ldcg8(g_hr_h + ((size_t)r[j] * NPAD + (size_t)s[j]) * DIM + lane * 4);
#pragma unroll
    for (int j = 0; j < 4; j++) {
        if (j < cnt) {
            float2 f01 = __half22float2(*(__half2*)&raw[j].x);
            float2 f23 = __half22float2(*(__half2*)&raw[j].y);
            float* q = out + (size_t)d[j] * DIM + lane * 4;
            asm volatile("red.global.add.v4.f32 [%0], {%1, %2, %3, %4};"
                         :: "l"(q), "f"(f01.x), "f"(f01.y), "f"(f23.x), "f"(f23.y)
                         : "memory");
        }
    }
}

__global__ void rgcn_relu(float* __restrict__ out, int n4) {
    int i = blockIdx.x * blockDim.x + threadIdx.x;
    if (i < n4) {
        float4 v = ((float4*)out)[i];
        v.x = fmaxf(v.x, 0.0f); v.y = fmaxf(v.y, 0.0f);
        v.z = fmaxf(v.z, 0.0f); v.w = fmaxf(v.w, 0.0f);
        ((float4*)out)[i] = v;
    }
}

// ---------------------------------------------------------------------------
extern "C" void kernel_launch(void* const* d_in, const int* in_sizes, int n_in,
                              void* d_out, int out_size) {
    const float* x    = (const float*)d_in[0];
    const float* w    = (const float*)d_in[1];
    const float* sw   = (const float*)d_in[2];
    const float* bias = (const float*)d_in[3];
    const int* ei = (const int*)d_in[4];
    const int* et = (const int*)d_in[5];

    int n_nodes = in_sizes[0] / DIM;
    int n_edges = in_sizes[5];
    float* out = (float*)d_out;

    cudaFuncSetAttribute(rgcn_gemm_mma, cudaFuncAttributeMaxDynamicSharedMemorySize,
                         SMEM_BYTES);

    int cw = (NREL * 8 * 16 * 32 + 255) / 256;
    conv_w<<<cw, 256>>>(w, sw);

    int nb = (n_nodes + 127) / 128;
    rgcn_gemm_mma<<<nb, NTHREADS, SMEM_BYTES>>>(x, bias, out, n_nodes);

    int n_warps = (n_edges + 3) / 4;
    long long total_threads = (long long)n_warps * 32;
    int blocks = (int)((total_threads + 255) / 256);
    rgcn_scatter<<<blocks, 256>>>(ei, et, out, n_edges);

    int n4 = n_nodes * DIM / 4;
    rgcn_relu<<<(n4 + 255) / 256, 256>>>(out, n4);
}